// round 11
// baseline (speedup 1.0000x reference)
#include <cuda_runtime.h>

// Problem constants
#define BQ 32
#define HWX 4096          // 64*64
#define CHX 32            // half channels per branch
#define COX 64            // branch output channels

// ---------------- scratch (device globals; no allocation) ----------------
__device__ float g_h [4L*BQ*CHX*HWX];
__device__ float g_c1[12L*BQ*CHX*HWX];
__device__ float g_c2[8L*BQ*COX*HWX];
__device__ float g_v [4L*BQ*COX*HWX];
__device__ float g_k1 [4L*BQ*COX*CHX*9];
__device__ float g_k2 [4L*BQ*COX*CHX];
__device__ float g_k2p[4L*BQ*8*COX*CHX];
__device__ float g_bnpart[4096];
__device__ float g_stats_pre [2*128];
__device__ float g_stats_post[4*128];

typedef unsigned long long u64;

__device__ __forceinline__ u64 fma2(u64 a, u64 b, u64 c) {
    u64 d; asm("fma.rn.f32x2 %0, %1, %2, %3;" : "=l"(d) : "l"(a), "l"(b), "l"(c)); return d;
}
__device__ __forceinline__ float2 unpack2(u64 v) {
    float lo, hi; asm("mov.b64 {%0,%1}, %2;" : "=f"(lo), "=f"(hi) : "l"(v));
    return make_float2(lo, hi);
}

// ---------------- batchnorm stats, stage 1 ----------------
__global__ __launch_bounds__(256)
void bn_part_kernel(const float* __restrict__ in, long yStride, int coffMul,
                    int Cimg, float* __restrict__ part)
{
    const int c  = blockIdx.x;
    const int yy = blockIdx.y;
    const int ch = blockIdx.z;
    const int C  = gridDim.x;
    const int tid = threadIdx.x;
    const float4* p4 = (const float4*)(in + yy*yStride);
    const int coff = yy*coffMul;
    float s = 0.f, sq = 0.f;
    #pragma unroll
    for (int bb = 0; bb < 4; bb++) {
        int b = ch*4 + bb;
        long base = ((long)(b*Cimg + coff + c)) << 10;
        for (int q = tid; q < 1024; q += 256) {
            float4 v = p4[base + q];
            s  += v.x + v.y + v.z + v.w;
            sq += v.x*v.x + v.y*v.y + v.z*v.z + v.w*v.w;
        }
    }
    __shared__ float rs[256], rq[256];
    rs[tid] = s; rq[tid] = sq;
    __syncthreads();
    for (int st = 128; st > 0; st >>= 1) {
        if (tid < st) { rs[tid] += rs[tid+st]; rq[tid] += rq[tid+st]; }
        __syncthreads();
    }
    if (tid == 0) {
        part[((yy*8 + ch)*C + c)*2 + 0] = rs[0];
        part[((yy*8 + ch)*C + c)*2 + 1] = rq[0];
    }
}

// ---------------- batchnorm stats, stage 2 ----------------
__global__ __launch_bounds__(256)
void bn_fin_kernel(const float* __restrict__ part, int C, int Y,
                   float* __restrict__ stats)
{
    int tid = threadIdx.x;
    if (tid >= Y*C) return;
    int yy = tid / C, c = tid % C;
    float s = 0.f, sq = 0.f;
    #pragma unroll
    for (int ch = 0; ch < 8; ch++) {
        s  += part[((yy*8 + ch)*C + c)*2 + 0];
        sq += part[((yy*8 + ch)*C + c)*2 + 1];
    }
    float mean = s * (1.f/131072.f);
    float var  = sq * (1.f/131072.f) - mean*mean;
    stats[yy*128 + c]      = mean;
    stats[yy*128 + 64 + c] = rsqrtf(var + 1e-5f);
}

// ---------------- pre-norm apply ----------------
__global__ __launch_bounds__(256)
void pre_apply_kernel(const float* __restrict__ x, const float* __restrict__ stats,
                      const float* __restrict__ a_pre, float* __restrict__ h)
{
    int idx = blockIdx.x * 256 + threadIdx.x;
    if (idx >= 4*BQ*CHX*1024) return;
    int q  = idx & 1023;
    int c  = (idx >> 10) & 31;
    int b  = (idx >> 15) & 31;
    int br = idx >> 20;
    int half = br & 1;
    float ap   = a_pre[br];
    float mean = stats[half*128 + c];
    float rstd = stats[half*128 + 64 + c];
    float sA = 0.5f*rstd + 0.01f*ap;
    float sB = -0.5f*mean*rstd;
    float4 v = ((const float4*)x)[(((long)(b*64 + half*32 + c)) << 10) + q];
    float4 o;
    o.x = sA*v.x + sB; o.y = sA*v.y + sB; o.z = sA*v.z + sB; o.w = sA*v.w + sB;
    ((float4*)h)[idx] = o;
}

// ---------------- shared conv body ----------------
// Double-buffered DUPLICATED input tile: s_in[idx] = (v,v) as float2, so the
// f32x2 multiplicand comes straight from LDS.128 with zero MOVs.
// Sliding 2-row window (dA/dB) keeps the live register set small.
#define LOADROW(D, P) { \
    ulonglong2 _t0 = *reinterpret_cast<const ulonglong2*>(P); \
    ulonglong2 _t1 = *reinterpret_cast<const ulonglong2*>((P) + 2); \
    (D)[0] = _t0.x; (D)[1] = _t0.y; (D)[2] = _t1.x; (D)[3] = _t1.y; }

#define TAPROW(KY, TOP, BOT) { \
    _Pragma("unroll") \
    for (int kx = 0; kx < 3; kx++) { \
        const u64* wt = (const u64*)(wci + ((KY)*3 + kx)*8); \
        _Pragma("unroll") \
        for (int j2 = 0; j2 < 4; j2++) { \
            u64 w2 = wt[j2]; \
            acc[j2][0] = fma2((TOP)[kx],   w2, acc[j2][0]); \
            acc[j2][1] = fma2((TOP)[kx+1], w2, acc[j2][1]); \
            acc[j2][2] = fma2((BOT)[kx],   w2, acc[j2][2]); \
            acc[j2][3] = fma2((BOT)[kx+1], w2, acc[j2][3]); \
        } } }

__device__ __forceinline__ void conv_body(const float* __restrict__ in,
                                          const float* s_w,
                                          float2* s_in0, float2* s_in1,
                                          float* __restrict__ out,
                                          int co0, int ty0, int tx0, int tid)
{
    const int px = (tid & 15) << 1;
    const int py = (tid >> 4) << 1;
    u64 acc[4][4];
    #pragma unroll
    for (int a = 0; a < 4; a++)
        #pragma unroll
        for (int p = 0; p < 4; p++) acc[a][p] = 0ULL;

    // invariant tile-load descriptors (idx strided by 256 over 34*34=1156)
    int  loff[5];
    bool lval[5];
    #pragma unroll
    for (int k = 0; k < 5; k++) {
        int idx = tid + k*256;
        int r = idx / 34, cc = idx - r*34;
        int gy = ty0 - 1 + r, gx = tx0 - 1 + cc;
        lval[k] = (idx < 1156) && ((unsigned)gy < 64u) && ((unsigned)gx < 64u);
        loff[k] = (gy << 6) + gx;
    }
    float ld[5];

#define CONV_FETCH(CI) { _Pragma("unroll") \
    for (int k = 0; k < 5; k++) ld[k] = lval[k] ? in[((CI) << 12) + loff[k]] : 0.f; }
#define CONV_STORE(BUF) { _Pragma("unroll") \
    for (int k = 0; k < 5; k++) { int idx = tid + k*256; \
        if (idx < 1156) (BUF)[idx] = make_float2(ld[k], ld[k]); } }

    CONV_FETCH(0);
    CONV_STORE(s_in0);
    __syncthreads();

    const int rb = py*34 + px;
    for (int ci = 0; ci < 32; ci++) {
        float2* cur = (ci & 1) ? s_in1 : s_in0;
        float2* nxt = (ci & 1) ? s_in0 : s_in1;
        if (ci < 31) CONV_FETCH(ci + 1);     // LDGs in flight behind the FMA chain

        const float2* rbase = cur + rb;
        const float* wci = s_w + ci*72;
        u64 dA[4], dB[4];
        LOADROW(dA, rbase);                  // row py+0
        LOADROW(dB, rbase + 34);             // row py+1
        TAPROW(0, dA, dB);
        LOADROW(dA, rbase + 68);             // row py+2
        TAPROW(1, dB, dA);
        LOADROW(dB, rbase + 102);            // row py+3
        TAPROW(2, dA, dB);

        if (ci < 31) CONV_STORE(nxt);
        __syncthreads();
    }
#undef CONV_FETCH
#undef CONV_STORE

    #pragma unroll
    for (int j2 = 0; j2 < 4; j2++)
        #pragma unroll
        for (int p = 0; p < 4; p++) {
            float2 v = unpack2(acc[j2][p]);
            int y  = ty0 + py + (p >> 1);
            int xx = tx0 + px + (p & 1);
            long o0 = ((long)(co0 + (j2 << 1)) << 12) + (y << 6) + xx;
            out[o0]        = v.x;
            out[o0 + 4096] = v.y;
        }
}

// ---------------- static conv3x3 pad1, Ci=32, batched over (cv, br, b) ----------------
__global__ __launch_bounds__(256, 4)
void conv_static_kernel(const float* __restrict__ h,
                        const float* __restrict__ wA, const float* __restrict__ wB,
                        const float* __restrict__ wC,
                        float* __restrict__ out, int Co)
{
    __shared__ __align__(16) float2 s_in0[34*34], s_in1[34*34];
    __shared__ __align__(16) float s_w[32*9*8];
    const int zz = blockIdx.z;
    const int b    = zz & 31;
    const int rest = zz >> 5;
    const int br   = rest & 3;
    const int cv   = rest >> 2;
    const int co0  = blockIdx.y << 3;
    const int ty0  = (blockIdx.x >> 1) << 5;
    const int tx0  = (blockIdx.x & 1) << 5;
    const int tid  = threadIdx.x;

    const float* w = (cv == 0 ? wA : (cv == 1 ? wB : wC)) + (long)br*Co*32*9;
    const float* in = h + ((long)(br*32 + b))*CHX*HWX;
    float* o = out + ((long)((cv*4 + br)*32 + b))*(long)Co*HWX;

    for (int idx = tid; idx < 32*9*8; idx += 256) {
        int j = idx & 7; int r = idx >> 3; int t = r % 9; int ci = r / 9;
        s_w[idx] = w[((co0 + j)*32 + ci)*9 + t];
    }
    conv_body(in, s_w, s_in0, s_in1, o, co0, ty0, tx0, tid);
}

// ---------------- dynamic conv: weights = k2*(k1 + aw) computed inline ----------------
__global__ __launch_bounds__(256, 4)
void conv_dyn_kernel(const float* __restrict__ c1, const float* __restrict__ k1,
                     const float* __restrict__ k2, const float* __restrict__ aw,
                     float* __restrict__ v)
{
    __shared__ __align__(16) float2 s_in0[34*34], s_in1[34*34];
    __shared__ __align__(16) float s_w[32*9*8];
    const int zz = blockIdx.z;
    const int b  = zz & 31;
    const int br = zz >> 5;
    const int g  = br*32 + b;
    const int co0 = blockIdx.y << 3;
    const int ty0 = (blockIdx.x >> 1) << 5;
    const int tx0 = (blockIdx.x & 1) << 5;
    const int tid = threadIdx.x;

    const float* in = c1 + ((long)((8 + br)*32 + b))*CHX*HWX;   // wconv conv output
    float* o = v + ((long)g)*COX*HWX;
    const long kb  = (long)g*64*32;
    const long awb = (long)br*64*32*9;

    for (int idx = tid; idx < 32*9*8; idx += 256) {
        int j = idx & 7; int r = idx >> 3; int t = r % 9; int ci = r / 9;
        int oi = (co0 + j)*32 + ci;
        float kk2 = k2[kb + oi];
        float kk1 = k1[(kb + oi)*9 + t];
        float w_  = aw[awb + (long)oi*9 + t];
        s_w[idx] = kk2 * (kk1 + w_);
    }
    conv_body(in, s_w, s_in0, s_in1, o, co0, ty0, tx0, tid);
}

// ---------------- k1 attention reduction ----------------
__global__ __launch_bounds__(256)
void k1_reduce_kernel(const float* __restrict__ c1, const float* __restrict__ c2,
                      float* __restrict__ k1out)
{
    __shared__ float s1[32*63];
    __shared__ float s2[64*63];
    const int t  = blockIdx.x;          // 0..8
    const int b  = blockIdx.y;
    const int br = blockIdx.z;
    const int g  = br*32 + b;
    const int dy = t / 3, dx = t % 3;
    const int tid = threadIdx.x;
    const int i  = tid & 31;
    const int og = tid >> 5;
    const float* p1 = c1 + ((long)(br*32 + b))*CHX*HWX;
    const float* p2 = c2 + ((long)(br*32 + b))*COX*HWX;
    float acc[8];
    #pragma unroll
    for (int j = 0; j < 8; j++) acc[j] = 0.f;

    for (int cc = 0; cc < 7; cc++) {
        __syncthreads();
        for (int idx = tid; idx < 32*63; idx += 256) {
            int ch = idx / 63, q = idx - ch*63;
            int ty = cc*3 + q/21, tx = q % 21;
            s1[idx] = p1[(ch << 12) + ((3*ty + dy) << 6) + 3*tx + dx];
        }
        for (int idx = tid; idx < 64*63; idx += 256) {
            int ch = idx / 63, q = idx - ch*63;
            int ty = cc*3 + q/21, tx = q % 21;
            s2[idx] = p2[(ch << 12) + ((3*ty + dy) << 6) + 3*tx + dx];
        }
        __syncthreads();
        for (int q = 0; q < 63; q++) {
            float v1 = s1[i*63 + q];
            #pragma unroll
            for (int j = 0; j < 8; j++)
                acc[j] += v1 * s2[(og*8 + j)*63 + q];
        }
    }
    #pragma unroll
    for (int j = 0; j < 8; j++)
        k1out[(((long)g*64 + og*8 + j)*32 + i)*9 + t] = acc[j] * 0.05892556509887896f;
}

// ---------------- k2 partial sums ----------------
__global__ __launch_bounds__(256)
void k2_partial_kernel(const float* __restrict__ c1, const float* __restrict__ c2,
                       float* __restrict__ part)
{
    __shared__ float s1[32*65];
    __shared__ float s2[64*64];
    const int pt = blockIdx.x;
    const int b  = blockIdx.y;
    const int br = blockIdx.z;
    const int g  = br*32 + b;
    const int tid = threadIdx.x;
    const int i  = tid & 31;
    const int og = tid >> 5;
    const float* p1 = c1 + ((long)((4 + br)*32 + b))*CHX*HWX;
    const float* p2 = c2 + ((long)((4 + br)*32 + b))*COX*HWX;
    float acc[8];
    #pragma unroll
    for (int j = 0; j < 8; j++) acc[j] = 0.f;

    for (int cc = 0; cc < 8; cc++) {
        __syncthreads();
        int pbase = pt*512 + cc*64;
        for (int idx = tid; idx < 32*64; idx += 256) {
            int ch = idx >> 6, q = idx & 63;
            s1[ch*65 + q] = p1[(ch << 12) + pbase + q];
        }
        for (int idx = tid; idx < 64*64; idx += 256) {
            int ch = idx >> 6, q = idx & 63;
            s2[idx] = p2[(ch << 12) + pbase + q];
        }
        __syncthreads();
        for (int q = 0; q < 64; q++) {
            float v1 = s1[i*65 + q];
            #pragma unroll
            for (int j = 0; j < 8; j++)
                acc[j] += v1 * s2[(og*8 + j)*64 + q];
        }
    }
    #pragma unroll
    for (int j = 0; j < 8; j++)
        part[(((long)(g*8 + pt)*64) + og*8 + j)*32 + i] = acc[j];
}

// ---------------- k2 softmax ----------------
__global__ __launch_bounds__(256)
void k2_softmax_kernel(const float* __restrict__ part, float* __restrict__ k2)
{
    const int warp = threadIdx.x >> 5;
    const int lane = threadIdx.x & 31;
    const int row  = blockIdx.x*8 + warp;
    const int g = row >> 6, o = row & 63;
    float s = 0.f;
    #pragma unroll
    for (int pt = 0; pt < 8; pt++)
        s += part[(((long)(g*8 + pt)*64) + o)*32 + lane];
    float a = s * 0.17677669529663687f;
    float m = a;
    #pragma unroll
    for (int off = 16; off > 0; off >>= 1)
        m = fmaxf(m, __shfl_xor_sync(0xffffffffu, m, off));
    float e = expf(a - m);
    float sum = e;
    #pragma unroll
    for (int off = 16; off > 0; off >>= 1)
        sum += __shfl_xor_sync(0xffffffffu, sum, off);
    k2[((long)g*64 + o)*32 + lane] = e / sum;
}

// ---------------- finalize ----------------
__global__ __launch_bounds__(256)
void finalize_kernel(const float* __restrict__ v, const float* __restrict__ stats,
                     const float* __restrict__ a_post, const float* __restrict__ x,
                     const float* __restrict__ cm, float* __restrict__ out)
{
    int idx = blockIdx.x*256 + threadIdx.x;
    if (idx >= BQ*COX*1024) return;
    int c = (idx >> 10) & 63;
    int b = idx >> 16;
    long qoff = (long)(idx & 0xFFFF);

    float4 y[4];
    #pragma unroll
    for (int br = 0; br < 4; br++) {
        float ap   = a_post[br];
        float mean = stats[br*128 + c];
        float rstd = stats[br*128 + 64 + c];
        float sA = 0.5f*rstd + 0.6f*ap;
        float sB = -0.5f*mean*rstd;
        float4 vv = ((const float4*)v)[((long)(br*32 + b) << 16) + qoff];
        y[br].x = sA*vv.x + sB; y[br].y = sA*vv.y + sB;
        y[br].z = sA*vv.z + sB; y[br].w = sA*vv.w + sB;
    }
    float4 xv = ((const float4*)x)[idx];
    float k = 0.99f * cm[0];
    const float is3 = 0.5773502691896258f;
    float4 o;
    o.x = k*xv.x + (y[0].x + y[1].x + y[2].x*y[3].x)*is3;
    o.y = k*xv.y + (y[0].y + y[1].y + y[2].y*y[3].y)*is3;
    o.z = k*xv.z + (y[0].z + y[1].z + y[2].z*y[3].z)*is3;
    o.w = k*xv.w + (y[0].w + y[1].w + y[2].w*y[3].w)*is3;
    ((float4*)out)[idx] = o;
}

// ---------------- launch ----------------
extern "C" void kernel_launch(void* const* d_in, const int* in_sizes, int n_in,
                              void* d_out, int out_size)
{
    const float* x      = (const float*)d_in[0];
    const float* wk1c1  = (const float*)d_in[1];
    const float* wk1c2  = (const float*)d_in[2];
    const float* wk2c1  = (const float*)d_in[3];
    const float* wk2c2  = (const float*)d_in[4];
    const float* wconv  = (const float*)d_in[5];
    const float* attn_w = (const float*)d_in[6];
    const float* a_pre  = (const float*)d_in[7];
    const float* a_post = (const float*)d_in[8];
    const float* cm     = (const float*)d_in[9];
    float* out = (float*)d_out;

    float *h, *c1, *c2, *v, *k1, *k2, *k2p, *bnp, *stp, *sto;
    cudaGetSymbolAddress((void**)&h,   g_h);
    cudaGetSymbolAddress((void**)&c1,  g_c1);
    cudaGetSymbolAddress((void**)&c2,  g_c2);
    cudaGetSymbolAddress((void**)&v,   g_v);
    cudaGetSymbolAddress((void**)&k1,  g_k1);
    cudaGetSymbolAddress((void**)&k2,  g_k2);
    cudaGetSymbolAddress((void**)&k2p, g_k2p);
    cudaGetSymbolAddress((void**)&bnp, g_bnpart);
    cudaGetSymbolAddress((void**)&stp, g_stats_pre);
    cudaGetSymbolAddress((void**)&sto, g_stats_post);

    // 1. pre-norm stats for both halves of x (two-stage, deterministic)
    bn_part_kernel<<<dim3(32, 2, 8), 256>>>(x, 0L, 32, 64, bnp);
    bn_fin_kernel<<<1, 256>>>(bnp, 32, 2, stp);
    // 2. h for all 4 branches
    pre_apply_kernel<<<16384, 256>>>(x, stp, a_pre, h);
    // 3. all 32-out static convs (wk1c1, wk2c1, wconv) x 4 branches
    conv_static_kernel<<<dim3(4, 4, 384), 256>>>(h, wk1c1, wk2c1, wconv, c1, 32);
    // 4. all 64-out static convs (wk1c2, wk2c2) x 4 branches
    conv_static_kernel<<<dim3(4, 8, 256), 256>>>(h, wk1c2, wk2c2, wk2c2, c2, 64);
    // 5. k1 attention reduction
    k1_reduce_kernel<<<dim3(9, BQ, 4), 256>>>(c1, c2, k1);
    // 6-7. k2 attention reduction + softmax
    k2_partial_kernel<<<dim3(8, BQ, 4), 256>>>(c1, c2, k2p);
    k2_softmax_kernel<<<1024, 256>>>(k2p, k2);
    // 8. dynamic attention conv (ak computed inline while staging weights)
    conv_dyn_kernel<<<dim3(4, 8, 128), 256>>>(c1, k1, k2, attn_w, v);
    // 9. post-norm stats per branch (two-stage)
    bn_part_kernel<<<dim3(64, 4, 8), 256>>>(v, (long)BQ*COX*HWX, 0, 64, bnp);
    bn_fin_kernel<<<1, 256>>>(bnp, 64, 4, sto);
    // 10. fused post-norm + branch combine
    finalize_kernel<<<8192, 256>>>(v, sto, a_post, x, cm, out);

    (void)in_sizes; (void)n_in; (void)out_size;
}

// round 16
// speedup vs baseline: 1.1822x; 1.1822x over previous
#include <cuda_runtime.h>

// Problem constants
#define BQ 32
#define HWX 4096          // 64*64
#define CHX 32            // half channels per branch
#define COX 64            // branch output channels

// ---------------- scratch (device globals; no allocation) ----------------
__device__ float g_h [4L*BQ*CHX*HWX];
__device__ float g_c1[12L*BQ*CHX*HWX];
__device__ float g_c2[8L*BQ*COX*HWX];
__device__ float g_v [4L*BQ*COX*HWX];
__device__ float g_k1 [4L*BQ*COX*CHX*9];
__device__ float g_k2 [4L*BQ*COX*CHX];
__device__ float g_k2p[4L*BQ*8*COX*CHX];
__device__ float g_bnpart[4096];
__device__ float g_stats_pre [2*128];
__device__ float g_stats_post[4*128];

typedef unsigned long long u64;

__device__ __forceinline__ u64 pack2(float lo, float hi) {
    u64 r; asm("mov.b64 %0, {%1,%2};" : "=l"(r) : "f"(lo), "f"(hi)); return r;
}
__device__ __forceinline__ u64 fma2(u64 a, u64 b, u64 c) {
    u64 d; asm("fma.rn.f32x2 %0, %1, %2, %3;" : "=l"(d) : "l"(a), "l"(b), "l"(c)); return d;
}
__device__ __forceinline__ float2 unpack2(u64 v) {
    float lo, hi; asm("mov.b64 {%0,%1}, %2;" : "=f"(lo), "=f"(hi) : "l"(v));
    return make_float2(lo, hi);
}

// ---------------- batchnorm stats, stage 1 ----------------
__global__ __launch_bounds__(256)
void bn_part_kernel(const float* __restrict__ in, long yStride, int coffMul,
                    int Cimg, float* __restrict__ part)
{
    const int c  = blockIdx.x;
    const int yy = blockIdx.y;
    const int ch = blockIdx.z;
    const int C  = gridDim.x;
    const int tid = threadIdx.x;
    const float4* p4 = (const float4*)(in + yy*yStride);
    const int coff = yy*coffMul;
    float s = 0.f, sq = 0.f;
    #pragma unroll
    for (int bb = 0; bb < 4; bb++) {
        int b = ch*4 + bb;
        long base = ((long)(b*Cimg + coff + c)) << 10;
        for (int q = tid; q < 1024; q += 256) {
            float4 v = p4[base + q];
            s  += v.x + v.y + v.z + v.w;
            sq += v.x*v.x + v.y*v.y + v.z*v.z + v.w*v.w;
        }
    }
    __shared__ float rs[256], rq[256];
    rs[tid] = s; rq[tid] = sq;
    __syncthreads();
    for (int st = 128; st > 0; st >>= 1) {
        if (tid < st) { rs[tid] += rs[tid+st]; rq[tid] += rq[tid+st]; }
        __syncthreads();
    }
    if (tid == 0) {
        part[((yy*8 + ch)*C + c)*2 + 0] = rs[0];
        part[((yy*8 + ch)*C + c)*2 + 1] = rq[0];
    }
}

// ---------------- batchnorm stats, stage 2 ----------------
__global__ __launch_bounds__(256)
void bn_fin_kernel(const float* __restrict__ part, int C, int Y,
                   float* __restrict__ stats)
{
    int tid = threadIdx.x;
    if (tid >= Y*C) return;
    int yy = tid / C, c = tid % C;
    float s = 0.f, sq = 0.f;
    #pragma unroll
    for (int ch = 0; ch < 8; ch++) {
        s  += part[((yy*8 + ch)*C + c)*2 + 0];
        sq += part[((yy*8 + ch)*C + c)*2 + 1];
    }
    float mean = s * (1.f/131072.f);
    float var  = sq * (1.f/131072.f) - mean*mean;
    stats[yy*128 + c]      = mean;
    stats[yy*128 + 64 + c] = rsqrtf(var + 1e-5f);
}

// ---------------- pre-norm apply ----------------
__global__ __launch_bounds__(256)
void pre_apply_kernel(const float* __restrict__ x, const float* __restrict__ stats,
                      const float* __restrict__ a_pre, float* __restrict__ h)
{
    int idx = blockIdx.x * 256 + threadIdx.x;
    if (idx >= 4*BQ*CHX*1024) return;
    int q  = idx & 1023;
    int c  = (idx >> 10) & 31;
    int b  = (idx >> 15) & 31;
    int br = idx >> 20;
    int half = br & 1;
    float ap   = a_pre[br];
    float mean = stats[half*128 + c];
    float rstd = stats[half*128 + 64 + c];
    float sA = 0.5f*rstd + 0.01f*ap;
    float sB = -0.5f*mean*rstd;
    float4 v = ((const float4*)x)[(((long)(b*64 + half*32 + c)) << 10) + q];
    float4 o;
    o.x = sA*v.x + sB; o.y = sA*v.y + sB; o.z = sA*v.z + sB; o.w = sA*v.w + sB;
    ((float4*)h)[idx] = o;
}

// ---------------- shared conv body ----------------
// Plain-float double-buffered 34x34 tile (conflict-free LDS.64 reads),
// sliding 2-row window (dA/dB) for a small live register set.
#define LOADROWF(D, P) { \
    float2 _a = *reinterpret_cast<const float2*>(P); \
    float2 _b = *reinterpret_cast<const float2*>((P) + 2); \
    (D)[0] = pack2(_a.x, _a.x); (D)[1] = pack2(_a.y, _a.y); \
    (D)[2] = pack2(_b.x, _b.x); (D)[3] = pack2(_b.y, _b.y); }

#define TAPROW(KY, TOP, BOT) { \
    _Pragma("unroll") \
    for (int kx = 0; kx < 3; kx++) { \
        const u64* wt = (const u64*)(wci + ((KY)*3 + kx)*8); \
        _Pragma("unroll") \
        for (int j2 = 0; j2 < 4; j2++) { \
            u64 w2 = wt[j2]; \
            acc[j2][0] = fma2((TOP)[kx],   w2, acc[j2][0]); \
            acc[j2][1] = fma2((TOP)[kx+1], w2, acc[j2][1]); \
            acc[j2][2] = fma2((BOT)[kx],   w2, acc[j2][2]); \
            acc[j2][3] = fma2((BOT)[kx+1], w2, acc[j2][3]); \
        } } }

__device__ __forceinline__ void conv_body(const float* __restrict__ in,
                                          const float* s_w,
                                          float* s_in0, float* s_in1,
                                          float* __restrict__ out,
                                          int co0, int ty0, int tx0, int tid)
{
    const int px = (tid & 15) << 1;
    const int py = (tid >> 4) << 1;
    u64 acc[4][4];
    #pragma unroll
    for (int a = 0; a < 4; a++)
        #pragma unroll
        for (int p = 0; p < 4; p++) acc[a][p] = 0ULL;

    // invariant tile-load descriptors (idx strided by 256 over 34*34=1156)
    int  loff[5];
    bool lval[5];
    #pragma unroll
    for (int k = 0; k < 5; k++) {
        int idx = tid + k*256;
        int r = idx / 34, cc = idx - r*34;
        int gy = ty0 - 1 + r, gx = tx0 - 1 + cc;
        lval[k] = (idx < 1156) && ((unsigned)gy < 64u) && ((unsigned)gx < 64u);
        loff[k] = (gy << 6) + gx;
    }
    float ld[5];

#define CONV_FETCH(CI) { _Pragma("unroll") \
    for (int k = 0; k < 5; k++) ld[k] = lval[k] ? in[((CI) << 12) + loff[k]] : 0.f; }
#define CONV_STORE(BUF) { _Pragma("unroll") \
    for (int k = 0; k < 5; k++) { int idx = tid + k*256; if (idx < 1156) (BUF)[idx] = ld[k]; } }

    CONV_FETCH(0);
    CONV_STORE(s_in0);
    __syncthreads();

    const int rb = py*34 + px;
    for (int ci = 0; ci < 32; ci++) {
        float* cur = (ci & 1) ? s_in1 : s_in0;
        float* nxt = (ci & 1) ? s_in0 : s_in1;
        if (ci < 31) CONV_FETCH(ci + 1);     // LDGs in flight behind the FMA chain

        const float* rbase = cur + rb;
        const float* wci = s_w + ci*72;
        u64 dA[4], dB[4];
        LOADROWF(dA, rbase);                 // row py+0
        LOADROWF(dB, rbase + 34);            // row py+1
        TAPROW(0, dA, dB);
        LOADROWF(dA, rbase + 68);            // row py+2
        TAPROW(1, dB, dA);
        LOADROWF(dB, rbase + 102);           // row py+3
        TAPROW(2, dA, dB);

        if (ci < 31) CONV_STORE(nxt);
        __syncthreads();
    }
#undef CONV_FETCH
#undef CONV_STORE

    #pragma unroll
    for (int j2 = 0; j2 < 4; j2++)
        #pragma unroll
        for (int p = 0; p < 4; p++) {
            float2 v = unpack2(acc[j2][p]);
            int y  = ty0 + py + (p >> 1);
            int xx = tx0 + px + (p & 1);
            long o0 = ((long)(co0 + (j2 << 1)) << 12) + (y << 6) + xx;
            out[o0]        = v.x;
            out[o0 + 4096] = v.y;
        }
}

// ---------------- static conv3x3 pad1, Ci=32, batched over (cv, br, b) ----------------
__global__ __launch_bounds__(256, 4)
void conv_static_kernel(const float* __restrict__ h,
                        const float* __restrict__ wA, const float* __restrict__ wB,
                        const float* __restrict__ wC,
                        float* __restrict__ out, int Co)
{
    __shared__ __align__(8) float s_in0[34*34], s_in1[34*34];
    __shared__ __align__(8) float s_w[32*9*8];
    const int zz = blockIdx.z;
    const int b    = zz & 31;
    const int rest = zz >> 5;
    const int br   = rest & 3;
    const int cv   = rest >> 2;
    const int co0  = blockIdx.y << 3;
    const int ty0  = (blockIdx.x >> 1) << 5;
    const int tx0  = (blockIdx.x & 1) << 5;
    const int tid  = threadIdx.x;

    const float* w = (cv == 0 ? wA : (cv == 1 ? wB : wC)) + (long)br*Co*32*9;
    const float* in = h + ((long)(br*32 + b))*CHX*HWX;
    float* o = out + ((long)((cv*4 + br)*32 + b))*(long)Co*HWX;

    for (int idx = tid; idx < 32*9*8; idx += 256) {
        int j = idx & 7; int r = idx >> 3; int t = r % 9; int ci = r / 9;
        s_w[idx] = w[((co0 + j)*32 + ci)*9 + t];
    }
    conv_body(in, s_w, s_in0, s_in1, o, co0, ty0, tx0, tid);
}

// ---------------- dynamic conv: weights = k2*(k1 + aw) computed inline ----------------
__global__ __launch_bounds__(256, 4)
void conv_dyn_kernel(const float* __restrict__ c1, const float* __restrict__ k1,
                     const float* __restrict__ k2, const float* __restrict__ aw,
                     float* __restrict__ v)
{
    __shared__ __align__(8) float s_in0[34*34], s_in1[34*34];
    __shared__ __align__(8) float s_w[32*9*8];
    const int zz = blockIdx.z;
    const int b  = zz & 31;
    const int br = zz >> 5;
    const int g  = br*32 + b;
    const int co0 = blockIdx.y << 3;
    const int ty0 = (blockIdx.x >> 1) << 5;
    const int tx0 = (blockIdx.x & 1) << 5;
    const int tid = threadIdx.x;

    const float* in = c1 + ((long)((8 + br)*32 + b))*CHX*HWX;   // wconv conv output
    float* o = v + ((long)g)*COX*HWX;
    const long kb  = (long)g*64*32;
    const long awb = (long)br*64*32*9;

    for (int idx = tid; idx < 32*9*8; idx += 256) {
        int j = idx & 7; int r = idx >> 3; int t = r % 9; int ci = r / 9;
        int oi = (co0 + j)*32 + ci;
        float kk2 = k2[kb + oi];
        float kk1 = k1[(kb + oi)*9 + t];
        float w_  = aw[awb + (long)oi*9 + t];
        s_w[idx] = kk2 * (kk1 + w_);
    }
    conv_body(in, s_w, s_in0, s_in1, o, co0, ty0, tx0, tid);
}

// ---------------- k1 attention reduction ----------------
__global__ __launch_bounds__(256)
void k1_reduce_kernel(const float* __restrict__ c1, const float* __restrict__ c2,
                      float* __restrict__ k1out)
{
    __shared__ float s1[32*63];
    __shared__ float s2[64*63];
    const int t  = blockIdx.x;          // 0..8
    const int b  = blockIdx.y;
    const int br = blockIdx.z;
    const int g  = br*32 + b;
    const int dy = t / 3, dx = t % 3;
    const int tid = threadIdx.x;
    const int i  = tid & 31;
    const int og = tid >> 5;
    const float* p1 = c1 + ((long)(br*32 + b))*CHX*HWX;
    const float* p2 = c2 + ((long)(br*32 + b))*COX*HWX;
    float acc[8];
    #pragma unroll
    for (int j = 0; j < 8; j++) acc[j] = 0.f;

    for (int cc = 0; cc < 7; cc++) {
        __syncthreads();
        for (int idx = tid; idx < 32*63; idx += 256) {
            int ch = idx / 63, q = idx - ch*63;
            int ty = cc*3 + q/21, tx = q % 21;
            s1[idx] = p1[(ch << 12) + ((3*ty + dy) << 6) + 3*tx + dx];
        }
        for (int idx = tid; idx < 64*63; idx += 256) {
            int ch = idx / 63, q = idx - ch*63;
            int ty = cc*3 + q/21, tx = q % 21;
            s2[idx] = p2[(ch << 12) + ((3*ty + dy) << 6) + 3*tx + dx];
        }
        __syncthreads();
        for (int q = 0; q < 63; q++) {
            float v1 = s1[i*63 + q];
            #pragma unroll
            for (int j = 0; j < 8; j++)
                acc[j] += v1 * s2[(og*8 + j)*63 + q];
        }
    }
    #pragma unroll
    for (int j = 0; j < 8; j++)
        k1out[(((long)g*64 + og*8 + j)*32 + i)*9 + t] = acc[j] * 0.05892556509887896f;
}

// ---------------- k2 partial sums ----------------
__global__ __launch_bounds__(256)
void k2_partial_kernel(const float* __restrict__ c1, const float* __restrict__ c2,
                       float* __restrict__ part)
{
    __shared__ float s1[32*65];
    __shared__ float s2[64*64];
    const int pt = blockIdx.x;
    const int b  = blockIdx.y;
    const int br = blockIdx.z;
    const int g  = br*32 + b;
    const int tid = threadIdx.x;
    const int i  = tid & 31;
    const int og = tid >> 5;
    const float* p1 = c1 + ((long)((4 + br)*32 + b))*CHX*HWX;
    const float* p2 = c2 + ((long)((4 + br)*32 + b))*COX*HWX;
    float acc[8];
    #pragma unroll
    for (int j = 0; j < 8; j++) acc[j] = 0.f;

    for (int cc = 0; cc < 8; cc++) {
        __syncthreads();
        int pbase = pt*512 + cc*64;
        for (int idx = tid; idx < 32*64; idx += 256) {
            int ch = idx >> 6, q = idx & 63;
            s1[ch*65 + q] = p1[(ch << 12) + pbase + q];
        }
        for (int idx = tid; idx < 64*64; idx += 256) {
            int ch = idx >> 6, q = idx & 63;
            s2[idx] = p2[(ch << 12) + pbase + q];
        }
        __syncthreads();
        for (int q = 0; q < 64; q++) {
            float v1 = s1[i*65 + q];
            #pragma unroll
            for (int j = 0; j < 8; j++)
                acc[j] += v1 * s2[(og*8 + j)*64 + q];
        }
    }
    #pragma unroll
    for (int j = 0; j < 8; j++)
        part[(((long)(g*8 + pt)*64) + og*8 + j)*32 + i] = acc[j];
}

// ---------------- k2 softmax ----------------
__global__ __launch_bounds__(256)
void k2_softmax_kernel(const float* __restrict__ part, float* __restrict__ k2)
{
    const int warp = threadIdx.x >> 5;
    const int lane = threadIdx.x & 31;
    const int row  = blockIdx.x*8 + warp;
    const int g = row >> 6, o = row & 63;
    float s = 0.f;
    #pragma unroll
    for (int pt = 0; pt < 8; pt++)
        s += part[(((long)(g*8 + pt)*64) + o)*32 + lane];
    float a = s * 0.17677669529663687f;
    float m = a;
    #pragma unroll
    for (int off = 16; off > 0; off >>= 1)
        m = fmaxf(m, __shfl_xor_sync(0xffffffffu, m, off));
    float e = expf(a - m);
    float sum = e;
    #pragma unroll
    for (int off = 16; off > 0; off >>= 1)
        sum += __shfl_xor_sync(0xffffffffu, sum, off);
    k2[((long)g*64 + o)*32 + lane] = e / sum;
}

// ---------------- finalize ----------------
__global__ __launch_bounds__(256)
void finalize_kernel(const float* __restrict__ v, const float* __restrict__ stats,
                     const float* __restrict__ a_post, const float* __restrict__ x,
                     const float* __restrict__ cm, float* __restrict__ out)
{
    int idx = blockIdx.x*256 + threadIdx.x;
    if (idx >= BQ*COX*1024) return;
    int c = (idx >> 10) & 63;
    int b = idx >> 16;
    long qoff = (long)(idx & 0xFFFF);

    float4 y[4];
    #pragma unroll
    for (int br = 0; br < 4; br++) {
        float ap   = a_post[br];
        float mean = stats[br*128 + c];
        float rstd = stats[br*128 + 64 + c];
        float sA = 0.5f*rstd + 0.6f*ap;
        float sB = -0.5f*mean*rstd;
        float4 vv = ((const float4*)v)[((long)(br*32 + b) << 16) + qoff];
        y[br].x = sA*vv.x + sB; y[br].y = sA*vv.y + sB;
        y[br].z = sA*vv.z + sB; y[br].w = sA*vv.w + sB;
    }
    float4 xv = ((const float4*)x)[idx];
    float k = 0.99f * cm[0];
    const float is3 = 0.5773502691896258f;
    float4 o;
    o.x = k*xv.x + (y[0].x + y[1].x + y[2].x*y[3].x)*is3;
    o.y = k*xv.y + (y[0].y + y[1].y + y[2].y*y[3].y)*is3;
    o.z = k*xv.z + (y[0].z + y[1].z + y[2].z*y[3].z)*is3;
    o.w = k*xv.w + (y[0].w + y[1].w + y[2].w*y[3].w)*is3;
    ((float4*)out)[idx] = o;
}

// ---------------- launch ----------------
extern "C" void kernel_launch(void* const* d_in, const int* in_sizes, int n_in,
                              void* d_out, int out_size)
{
    const float* x      = (const float*)d_in[0];
    const float* wk1c1  = (const float*)d_in[1];
    const float* wk1c2  = (const float*)d_in[2];
    const float* wk2c1  = (const float*)d_in[3];
    const float* wk2c2  = (const float*)d_in[4];
    const float* wconv  = (const float*)d_in[5];
    const float* attn_w = (const float*)d_in[6];
    const float* a_pre  = (const float*)d_in[7];
    const float* a_post = (const float*)d_in[8];
    const float* cm     = (const float*)d_in[9];
    float* out = (float*)d_out;

    float *h, *c1, *c2, *v, *k1, *k2, *k2p, *bnp, *stp, *sto;
    cudaGetSymbolAddress((void**)&h,   g_h);
    cudaGetSymbolAddress((void**)&c1,  g_c1);
    cudaGetSymbolAddress((void**)&c2,  g_c2);
    cudaGetSymbolAddress((void**)&v,   g_v);
    cudaGetSymbolAddress((void**)&k1,  g_k1);
    cudaGetSymbolAddress((void**)&k2,  g_k2);
    cudaGetSymbolAddress((void**)&k2p, g_k2p);
    cudaGetSymbolAddress((void**)&bnp, g_bnpart);
    cudaGetSymbolAddress((void**)&stp, g_stats_pre);
    cudaGetSymbolAddress((void**)&sto, g_stats_post);

    // 1. pre-norm stats for both halves of x (two-stage, deterministic)
    bn_part_kernel<<<dim3(32, 2, 8), 256>>>(x, 0L, 32, 64, bnp);
    bn_fin_kernel<<<1, 256>>>(bnp, 32, 2, stp);
    // 2. h for all 4 branches
    pre_apply_kernel<<<16384, 256>>>(x, stp, a_pre, h);
    // 3. all 32-out static convs (wk1c1, wk2c1, wconv) x 4 branches
    conv_static_kernel<<<dim3(4, 4, 384), 256>>>(h, wk1c1, wk2c1, wconv, c1, 32);
    // 4. all 64-out static convs (wk1c2, wk2c2) x 4 branches
    conv_static_kernel<<<dim3(4, 8, 256), 256>>>(h, wk1c2, wk2c2, wk2c2, c2, 64);
    // 5. k1 attention reduction
    k1_reduce_kernel<<<dim3(9, BQ, 4), 256>>>(c1, c2, k1);
    // 6-7. k2 attention reduction + softmax
    k2_partial_kernel<<<dim3(8, BQ, 4), 256>>>(c1, c2, k2p);
    k2_softmax_kernel<<<1024, 256>>>(k2p, k2);
    // 8. dynamic attention conv (ak computed inline while staging weights)
    conv_dyn_kernel<<<dim3(4, 8, 128), 256>>>(c1, k1, k2, attn_w, v);
    // 9. post-norm stats per branch (two-stage)
    bn_part_kernel<<<dim3(64, 4, 8), 256>>>(v, (long)BQ*COX*HWX, 0, 64, bnp);
    bn_fin_kernel<<<1, 256>>>(bnp, 64, 4, sto);
    // 10. fused post-norm + branch combine
    finalize_kernel<<<8192, 256>>>(v, sto, a_post, x, cm, out);

    (void)in_sizes; (void)n_in; (void)out_size;
}

// round 17
// speedup vs baseline: 1.3085x; 1.1068x over previous
#include <cuda_runtime.h>

// Problem constants
#define BQ 32
#define HWX 4096          // 64*64
#define CHX 32            // half channels per branch
#define COX 64            // branch output channels

// ---------------- scratch (device globals; no allocation) ----------------
__device__ float g_h [4L*BQ*CHX*HWX];
__device__ float g_c1[12L*BQ*CHX*HWX];
__device__ float g_c2[8L*BQ*COX*HWX];
__device__ float g_v [4L*BQ*COX*HWX];
__device__ float g_k1 [4L*BQ*COX*CHX*9];
__device__ float g_k2 [4L*BQ*COX*CHX];
__device__ float g_k2p[4L*BQ*8*COX*CHX];
__device__ float g_bnpart[4096];
__device__ float g_stats_pre [2*128];
__device__ float g_stats_post[4*128];

typedef unsigned long long u64;

__device__ __forceinline__ u64 pack2(float lo, float hi) {
    u64 r; asm("mov.b64 %0, {%1,%2};" : "=l"(r) : "f"(lo), "f"(hi)); return r;
}
__device__ __forceinline__ u64 fma2(u64 a, u64 b, u64 c) {
    u64 d; asm("fma.rn.f32x2 %0, %1, %2, %3;" : "=l"(d) : "l"(a), "l"(b), "l"(c)); return d;
}
__device__ __forceinline__ float2 unpack2(u64 v) {
    float lo, hi; asm("mov.b64 {%0,%1}, %2;" : "=f"(lo), "=f"(hi) : "l"(v));
    return make_float2(lo, hi);
}

// ---------------- batchnorm stats, stage 1 ----------------
__global__ __launch_bounds__(256)
void bn_part_kernel(const float* __restrict__ in, long yStride, int coffMul,
                    int Cimg, float* __restrict__ part)
{
    const int c  = blockIdx.x;
    const int yy = blockIdx.y;
    const int ch = blockIdx.z;
    const int C  = gridDim.x;
    const int tid = threadIdx.x;
    const float4* p4 = (const float4*)(in + yy*yStride);
    const int coff = yy*coffMul;
    float s = 0.f, sq = 0.f;
    #pragma unroll
    for (int bb = 0; bb < 4; bb++) {
        int b = ch*4 + bb;
        long base = ((long)(b*Cimg + coff + c)) << 10;
        for (int q = tid; q < 1024; q += 256) {
            float4 v = p4[base + q];
            s  += v.x + v.y + v.z + v.w;
            sq += v.x*v.x + v.y*v.y + v.z*v.z + v.w*v.w;
        }
    }
    __shared__ float rs[256], rq[256];
    rs[tid] = s; rq[tid] = sq;
    __syncthreads();
    for (int st = 128; st > 0; st >>= 1) {
        if (tid < st) { rs[tid] += rs[tid+st]; rq[tid] += rq[tid+st]; }
        __syncthreads();
    }
    if (tid == 0) {
        part[((yy*8 + ch)*C + c)*2 + 0] = rs[0];
        part[((yy*8 + ch)*C + c)*2 + 1] = rq[0];
    }
}

// ---------------- batchnorm stats, stage 2 ----------------
__global__ __launch_bounds__(256)
void bn_fin_kernel(const float* __restrict__ part, int C, int Y,
                   float* __restrict__ stats)
{
    int tid = threadIdx.x;
    if (tid >= Y*C) return;
    int yy = tid / C, c = tid % C;
    float s = 0.f, sq = 0.f;
    #pragma unroll
    for (int ch = 0; ch < 8; ch++) {
        s  += part[((yy*8 + ch)*C + c)*2 + 0];
        sq += part[((yy*8 + ch)*C + c)*2 + 1];
    }
    float mean = s * (1.f/131072.f);
    float var  = sq * (1.f/131072.f) - mean*mean;
    stats[yy*128 + c]      = mean;
    stats[yy*128 + 64 + c] = rsqrtf(var + 1e-5f);
}

// ---------------- pre-norm apply ----------------
__global__ __launch_bounds__(256)
void pre_apply_kernel(const float* __restrict__ x, const float* __restrict__ stats,
                      const float* __restrict__ a_pre, float* __restrict__ h)
{
    int idx = blockIdx.x * 256 + threadIdx.x;
    if (idx >= 4*BQ*CHX*1024) return;
    int q  = idx & 1023;
    int c  = (idx >> 10) & 31;
    int b  = (idx >> 15) & 31;
    int br = idx >> 20;
    int half = br & 1;
    float ap   = a_pre[br];
    float mean = stats[half*128 + c];
    float rstd = stats[half*128 + 64 + c];
    float sA = 0.5f*rstd + 0.01f*ap;
    float sB = -0.5f*mean*rstd;
    float4 v = ((const float4*)x)[(((long)(b*64 + half*32 + c)) << 10) + q];
    float4 o;
    o.x = sA*v.x + sB; o.y = sA*v.y + sB; o.z = sA*v.z + sB; o.w = sA*v.w + sB;
    ((float4*)h)[idx] = o;
}

// ---------------- shared conv body ----------------
// 2 channels per pipeline stage: 16 barriers instead of 32, and each STS has
// >=1 full channel of FMA issue (288 slots) covering its LDG scoreboard.
// Plain-float tiles (conflict-free LDS.64), sliding 2-row window per channel.
#define LOADROWF(D, P) { \
    float2 _a = *reinterpret_cast<const float2*>(P); \
    float2 _b = *reinterpret_cast<const float2*>((P) + 2); \
    (D)[0] = pack2(_a.x, _a.x); (D)[1] = pack2(_a.y, _a.y); \
    (D)[2] = pack2(_b.x, _b.x); (D)[3] = pack2(_b.y, _b.y); }

#define TAPROW(KY, TOP, BOT) { \
    _Pragma("unroll") \
    for (int kx = 0; kx < 3; kx++) { \
        const u64* wt = (const u64*)(wci + ((KY)*3 + kx)*8); \
        _Pragma("unroll") \
        for (int j2 = 0; j2 < 4; j2++) { \
            u64 w2 = wt[j2]; \
            acc[j2][0] = fma2((TOP)[kx],   w2, acc[j2][0]); \
            acc[j2][1] = fma2((TOP)[kx+1], w2, acc[j2][1]); \
            acc[j2][2] = fma2((BOT)[kx],   w2, acc[j2][2]); \
            acc[j2][3] = fma2((BOT)[kx+1], w2, acc[j2][3]); \
        } } }

// full 3x3 accumulation for one channel tile (BASE = channel tile base, WCI = weights)
#define CONV_CHAN(BASE, WCI) { \
    const float* rbase = (BASE) + rb; \
    const float* wci = (WCI); \
    u64 dA[4], dB[4]; \
    LOADROWF(dA, rbase); \
    LOADROWF(dB, rbase + 34); \
    TAPROW(0, dA, dB); \
    LOADROWF(dA, rbase + 68); \
    TAPROW(1, dB, dA); \
    LOADROWF(dB, rbase + 102); \
    TAPROW(2, dA, dB); }

__device__ __forceinline__ void conv_body(const float* __restrict__ in,
                                          const float* s_w,
                                          float* s_in0, float* s_in1,
                                          float* __restrict__ out,
                                          int co0, int ty0, int tx0, int tid)
{
    const int px = (tid & 15) << 1;
    const int py = (tid >> 4) << 1;
    u64 acc[4][4];
    #pragma unroll
    for (int a = 0; a < 4; a++)
        #pragma unroll
        for (int p = 0; p < 4; p++) acc[a][p] = 0ULL;

    // invariant tile-load descriptors (idx strided by 256 over 34*34=1156)
    int  loff[5];
    bool lval[5];
    #pragma unroll
    for (int k = 0; k < 5; k++) {
        int idx = tid + k*256;
        int r = idx / 34, cc = idx - r*34;
        int gy = ty0 - 1 + r, gx = tx0 - 1 + cc;
        lval[k] = (idx < 1156) && ((unsigned)gy < 64u) && ((unsigned)gx < 64u);
        loff[k] = (gy << 6) + gx;
    }
    float ldA[5], ldB[5];

#define CONV_FETCH(CI, LD) { _Pragma("unroll") \
    for (int k = 0; k < 5; k++) (LD)[k] = lval[k] ? in[((CI) << 12) + loff[k]] : 0.f; }
#define CONV_STORE(BUF, LD) { _Pragma("unroll") \
    for (int k = 0; k < 5; k++) { int idx = tid + k*256; if (idx < 1156) (BUF)[idx] = (LD)[k]; } }

    // prologue: channels 0,1 into buffer 0
    CONV_FETCH(0, ldA);
    CONV_FETCH(1, ldB);
    CONV_STORE(s_in0,        ldA);
    CONV_STORE(s_in0 + 1156, ldB);
    __syncthreads();

    const int rb = py*34 + px;
    for (int cs = 0; cs < 16; cs++) {
        float* cur = (cs & 1) ? s_in1 : s_in0;
        float* nxt = (cs & 1) ? s_in0 : s_in1;
        if (cs < 15) {
            CONV_FETCH(2*cs + 2, ldA);       // LDGs in flight behind >=288 FMA slots
            CONV_FETCH(2*cs + 3, ldB);
        }
        CONV_CHAN(cur,        s_w + (2*cs    )*72);
        if (cs < 15) CONV_STORE(nxt,        ldA);
        CONV_CHAN(cur + 1156, s_w + (2*cs + 1)*72);
        if (cs < 15) CONV_STORE(nxt + 1156, ldB);
        __syncthreads();
    }
#undef CONV_FETCH
#undef CONV_STORE

    #pragma unroll
    for (int j2 = 0; j2 < 4; j2++)
        #pragma unroll
        for (int p = 0; p < 4; p++) {
            float2 v = unpack2(acc[j2][p]);
            int y  = ty0 + py + (p >> 1);
            int xx = tx0 + px + (p & 1);
            long o0 = ((long)(co0 + (j2 << 1)) << 12) + (y << 6) + xx;
            out[o0]        = v.x;
            out[o0 + 4096] = v.y;
        }
}

// ---------------- static conv3x3 pad1, Ci=32, batched over (cv, br, b) ----------------
__global__ __launch_bounds__(256, 4)
void conv_static_kernel(const float* __restrict__ h,
                        const float* __restrict__ wA, const float* __restrict__ wB,
                        const float* __restrict__ wC,
                        float* __restrict__ out, int Co)
{
    __shared__ __align__(8) float s_in0[2*34*34], s_in1[2*34*34];
    __shared__ __align__(8) float s_w[32*9*8];
    const int zz = blockIdx.z;
    const int b    = zz & 31;
    const int rest = zz >> 5;
    const int br   = rest & 3;
    const int cv   = rest >> 2;
    const int co0  = blockIdx.y << 3;
    const int ty0  = (blockIdx.x >> 1) << 5;
    const int tx0  = (blockIdx.x & 1) << 5;
    const int tid  = threadIdx.x;

    const float* w = (cv == 0 ? wA : (cv == 1 ? wB : wC)) + (long)br*Co*32*9;
    const float* in = h + ((long)(br*32 + b))*CHX*HWX;
    float* o = out + ((long)((cv*4 + br)*32 + b))*(long)Co*HWX;

    for (int idx = tid; idx < 32*9*8; idx += 256) {
        int j = idx & 7; int r = idx >> 3; int t = r % 9; int ci = r / 9;
        s_w[idx] = w[((co0 + j)*32 + ci)*9 + t];
    }
    conv_body(in, s_w, s_in0, s_in1, o, co0, ty0, tx0, tid);
}

// ---------------- dynamic conv: weights = k2*(k1 + aw) computed inline ----------------
__global__ __launch_bounds__(256, 4)
void conv_dyn_kernel(const float* __restrict__ c1, const float* __restrict__ k1,
                     const float* __restrict__ k2, const float* __restrict__ aw,
                     float* __restrict__ v)
{
    __shared__ __align__(8) float s_in0[2*34*34], s_in1[2*34*34];
    __shared__ __align__(8) float s_w[32*9*8];
    const int zz = blockIdx.z;
    const int b  = zz & 31;
    const int br = zz >> 5;
    const int g  = br*32 + b;
    const int co0 = blockIdx.y << 3;
    const int ty0 = (blockIdx.x >> 1) << 5;
    const int tx0 = (blockIdx.x & 1) << 5;
    const int tid = threadIdx.x;

    const float* in = c1 + ((long)((8 + br)*32 + b))*CHX*HWX;   // wconv conv output
    float* o = v + ((long)g)*COX*HWX;
    const long kb  = (long)g*64*32;
    const long awb = (long)br*64*32*9;

    for (int idx = tid; idx < 32*9*8; idx += 256) {
        int j = idx & 7; int r = idx >> 3; int t = r % 9; int ci = r / 9;
        int oi = (co0 + j)*32 + ci;
        float kk2 = k2[kb + oi];
        float kk1 = k1[(kb + oi)*9 + t];
        float w_  = aw[awb + (long)oi*9 + t];
        s_w[idx] = kk2 * (kk1 + w_);
    }
    conv_body(in, s_w, s_in0, s_in1, o, co0, ty0, tx0, tid);
}

// ---------------- k1 attention reduction ----------------
__global__ __launch_bounds__(256)
void k1_reduce_kernel(const float* __restrict__ c1, const float* __restrict__ c2,
                      float* __restrict__ k1out)
{
    __shared__ float s1[32*63];
    __shared__ float s2[64*63];
    const int t  = blockIdx.x;          // 0..8
    const int b  = blockIdx.y;
    const int br = blockIdx.z;
    const int g  = br*32 + b;
    const int dy = t / 3, dx = t % 3;
    const int tid = threadIdx.x;
    const int i  = tid & 31;
    const int og = tid >> 5;
    const float* p1 = c1 + ((long)(br*32 + b))*CHX*HWX;
    const float* p2 = c2 + ((long)(br*32 + b))*COX*HWX;
    float acc[8];
    #pragma unroll
    for (int j = 0; j < 8; j++) acc[j] = 0.f;

    for (int cc = 0; cc < 7; cc++) {
        __syncthreads();
        for (int idx = tid; idx < 32*63; idx += 256) {
            int ch = idx / 63, q = idx - ch*63;
            int ty = cc*3 + q/21, tx = q % 21;
            s1[idx] = p1[(ch << 12) + ((3*ty + dy) << 6) + 3*tx + dx];
        }
        for (int idx = tid; idx < 64*63; idx += 256) {
            int ch = idx / 63, q = idx - ch*63;
            int ty = cc*3 + q/21, tx = q % 21;
            s2[idx] = p2[(ch << 12) + ((3*ty + dy) << 6) + 3*tx + dx];
        }
        __syncthreads();
        for (int q = 0; q < 63; q++) {
            float v1 = s1[i*63 + q];
            #pragma unroll
            for (int j = 0; j < 8; j++)
                acc[j] += v1 * s2[(og*8 + j)*63 + q];
        }
    }
    #pragma unroll
    for (int j = 0; j < 8; j++)
        k1out[(((long)g*64 + og*8 + j)*32 + i)*9 + t] = acc[j] * 0.05892556509887896f;
}

// ---------------- k2 partial sums ----------------
__global__ __launch_bounds__(256)
void k2_partial_kernel(const float* __restrict__ c1, const float* __restrict__ c2,
                       float* __restrict__ part)
{
    __shared__ float s1[32*65];
    __shared__ float s2[64*64];
    const int pt = blockIdx.x;
    const int b  = blockIdx.y;
    const int br = blockIdx.z;
    const int g  = br*32 + b;
    const int tid = threadIdx.x;
    const int i  = tid & 31;
    const int og = tid >> 5;
    const float* p1 = c1 + ((long)((4 + br)*32 + b))*CHX*HWX;
    const float* p2 = c2 + ((long)((4 + br)*32 + b))*COX*HWX;
    float acc[8];
    #pragma unroll
    for (int j = 0; j < 8; j++) acc[j] = 0.f;

    for (int cc = 0; cc < 8; cc++) {
        __syncthreads();
        int pbase = pt*512 + cc*64;
        for (int idx = tid; idx < 32*64; idx += 256) {
            int ch = idx >> 6, q = idx & 63;
            s1[ch*65 + q] = p1[(ch << 12) + pbase + q];
        }
        for (int idx = tid; idx < 64*64; idx += 256) {
            int ch = idx >> 6, q = idx & 63;
            s2[idx] = p2[(ch << 12) + pbase + q];
        }
        __syncthreads();
        for (int q = 0; q < 64; q++) {
            float v1 = s1[i*65 + q];
            #pragma unroll
            for (int j = 0; j < 8; j++)
                acc[j] += v1 * s2[(og*8 + j)*64 + q];
        }
    }
    #pragma unroll
    for (int j = 0; j < 8; j++)
        part[(((long)(g*8 + pt)*64) + og*8 + j)*32 + i] = acc[j];
}

// ---------------- k2 softmax ----------------
__global__ __launch_bounds__(256)
void k2_softmax_kernel(const float* __restrict__ part, float* __restrict__ k2)
{
    const int warp = threadIdx.x >> 5;
    const int lane = threadIdx.x & 31;
    const int row  = blockIdx.x*8 + warp;
    const int g = row >> 6, o = row & 63;
    float s = 0.f;
    #pragma unroll
    for (int pt = 0; pt < 8; pt++)
        s += part[(((long)(g*8 + pt)*64) + o)*32 + lane];
    float a = s * 0.17677669529663687f;
    float m = a;
    #pragma unroll
    for (int off = 16; off > 0; off >>= 1)
        m = fmaxf(m, __shfl_xor_sync(0xffffffffu, m, off));
    float e = expf(a - m);
    float sum = e;
    #pragma unroll
    for (int off = 16; off > 0; off >>= 1)
        sum += __shfl_xor_sync(0xffffffffu, sum, off);
    k2[((long)g*64 + o)*32 + lane] = e / sum;
}

// ---------------- finalize ----------------
__global__ __launch_bounds__(256)
void finalize_kernel(const float* __restrict__ v, const float* __restrict__ stats,
                     const float* __restrict__ a_post, const float* __restrict__ x,
                     const float* __restrict__ cm, float* __restrict__ out)
{
    int idx = blockIdx.x*256 + threadIdx.x;
    if (idx >= BQ*COX*1024) return;
    int c = (idx >> 10) & 63;
    int b = idx >> 16;
    long qoff = (long)(idx & 0xFFFF);

    float4 y[4];
    #pragma unroll
    for (int br = 0; br < 4; br++) {
        float ap   = a_post[br];
        float mean = stats[br*128 + c];
        float rstd = stats[br*128 + 64 + c];
        float sA = 0.5f*rstd + 0.6f*ap;
        float sB = -0.5f*mean*rstd;
        float4 vv = ((const float4*)v)[((long)(br*32 + b) << 16) + qoff];
        y[br].x = sA*vv.x + sB; y[br].y = sA*vv.y + sB;
        y[br].z = sA*vv.z + sB; y[br].w = sA*vv.w + sB;
    }
    float4 xv = ((const float4*)x)[idx];
    float k = 0.99f * cm[0];
    const float is3 = 0.5773502691896258f;
    float4 o;
    o.x = k*xv.x + (y[0].x + y[1].x + y[2].x*y[3].x)*is3;
    o.y = k*xv.y + (y[0].y + y[1].y + y[2].y*y[3].y)*is3;
    o.z = k*xv.z + (y[0].z + y[1].z + y[2].z*y[3].z)*is3;
    o.w = k*xv.w + (y[0].w + y[1].w + y[2].w*y[3].w)*is3;
    ((float4*)out)[idx] = o;
}

// ---------------- launch ----------------
extern "C" void kernel_launch(void* const* d_in, const int* in_sizes, int n_in,
                              void* d_out, int out_size)
{
    const float* x      = (const float*)d_in[0];
    const float* wk1c1  = (const float*)d_in[1];
    const float* wk1c2  = (const float*)d_in[2];
    const float* wk2c1  = (const float*)d_in[3];
    const float* wk2c2  = (const float*)d_in[4];
    const float* wconv  = (const float*)d_in[5];
    const float* attn_w = (const float*)d_in[6];
    const float* a_pre  = (const float*)d_in[7];
    const float* a_post = (const float*)d_in[8];
    const float* cm     = (const float*)d_in[9];
    float* out = (float*)d_out;

    float *h, *c1, *c2, *v, *k1, *k2, *k2p, *bnp, *stp, *sto;
    cudaGetSymbolAddress((void**)&h,   g_h);
    cudaGetSymbolAddress((void**)&c1,  g_c1);
    cudaGetSymbolAddress((void**)&c2,  g_c2);
    cudaGetSymbolAddress((void**)&v,   g_v);
    cudaGetSymbolAddress((void**)&k1,  g_k1);
    cudaGetSymbolAddress((void**)&k2,  g_k2);
    cudaGetSymbolAddress((void**)&k2p, g_k2p);
    cudaGetSymbolAddress((void**)&bnp, g_bnpart);
    cudaGetSymbolAddress((void**)&stp, g_stats_pre);
    cudaGetSymbolAddress((void**)&sto, g_stats_post);

    // 1. pre-norm stats for both halves of x (two-stage, deterministic)
    bn_part_kernel<<<dim3(32, 2, 8), 256>>>(x, 0L, 32, 64, bnp);
    bn_fin_kernel<<<1, 256>>>(bnp, 32, 2, stp);
    // 2. h for all 4 branches
    pre_apply_kernel<<<16384, 256>>>(x, stp, a_pre, h);
    // 3. all 32-out static convs (wk1c1, wk2c1, wconv) x 4 branches
    conv_static_kernel<<<dim3(4, 4, 384), 256>>>(h, wk1c1, wk2c1, wconv, c1, 32);
    // 4. all 64-out static convs (wk1c2, wk2c2) x 4 branches
    conv_static_kernel<<<dim3(4, 8, 256), 256>>>(h, wk1c2, wk2c2, wk2c2, c2, 64);
    // 5. k1 attention reduction
    k1_reduce_kernel<<<dim3(9, BQ, 4), 256>>>(c1, c2, k1);
    // 6-7. k2 attention reduction + softmax
    k2_partial_kernel<<<dim3(8, BQ, 4), 256>>>(c1, c2, k2p);
    k2_softmax_kernel<<<1024, 256>>>(k2p, k2);
    // 8. dynamic attention conv (ak computed inline while staging weights)
    conv_dyn_kernel<<<dim3(4, 8, 128), 256>>>(c1, k1, k2, attn_w, v);
    // 9. post-norm stats per branch (two-stage)
    bn_part_kernel<<<dim3(64, 4, 8), 256>>>(v, (long)BQ*COX*HWX, 0, 64, bnp);
    bn_fin_kernel<<<1, 256>>>(bnp, 64, 4, sto);
    // 10. fused post-norm + branch combine
    finalize_kernel<<<8192, 256>>>(v, sto, a_post, x, cm, out);

    (void)in_sizes; (void)n_in; (void)out_size;
}